// round 15
// baseline (speedup 1.0000x reference)
#include <cuda_runtime.h>
#include <cuda_bf16.h>
#include <math.h>
#include <stdint.h>
#include <stddef.h>

// Problem constants
#define BATCH 512
#define LSEQ  128
#define HDIM  512
#define NTOK  (BATCH * LSEQ)   // 65536

// GEMM tile config (mma.sync path — base ISA only)
#define BM 128
#define BN 128
#define BK 32
#define SMEM_ROW_ELEM 40                    // 32 data + 8 pad (80B rows)
#define TILE_BYTES (BM * SMEM_ROW_ELEM * 2) // 10240 B per operand tile
#define STG_BYTES  (4 * TILE_BYTES)         // Ah,Al,Bh,Bl = 40960 B
#define NST 2
#define SMEM_DYN (NST * STG_BYTES)          // 81920 B -> 2 CTAs/SM

// ---------------------------------------------------------------------------
// Scratch (device globals: allocation-free, graph-capture safe)
// ---------------------------------------------------------------------------
__device__ float         g_h  [(size_t)NTOK * HDIM];        // fp32 h (residual)
__device__ __nv_bfloat16 g_hh [(size_t)NTOK * HDIM];        // h hi
__device__ __nv_bfloat16 g_hl [(size_t)NTOK * HDIM];        // h lo
__device__ float         g_zi [(size_t)NTOK * 2 * HDIM];    // in-proj out [z|xi]
__device__ __nv_bfloat16 g_uh [(size_t)NTOK * 2 * HDIM];    // u hi
__device__ __nv_bfloat16 g_ul [(size_t)NTOK * 2 * HDIM];    // u lo
__device__ float         g_t  [(size_t)NTOK * HDIM];        // pre-layernorm
__device__ __nv_bfloat16 g_wth[(size_t)1024 * 512];         // Wt hi [N,K]
__device__ __nv_bfloat16 g_wtl[(size_t)1024 * 512];         // Wt lo [N,K]
__device__ float         g_cwT[3 * 512];                    // conv_w transposed
__device__ float         g_xpT[16 * 512];                   // xp_w transposed
__device__ float g_reg[BATCH * HDIM];
__device__ float g_dec[BATCH * HDIM];

// ---------------------------------------------------------------------------
// helpers
// ---------------------------------------------------------------------------
__device__ __forceinline__ uint32_t smem_u32(const void* p) {
    return (uint32_t)__cvta_generic_to_shared(p);
}

__device__ __forceinline__ void bf16_split(float v, __nv_bfloat16& hi, __nv_bfloat16& lo) {
    hi = __float2bfloat16(v);
    lo = __float2bfloat16(v - __bfloat162float(hi));
}

__device__ __forceinline__ uint32_t pack_bf16x2(float a, float b) {
    __nv_bfloat162 p = __halves2bfloat162(__float2bfloat16(a), __float2bfloat16(b));
    return *(uint32_t*)&p;
}

#define LDSM4(r, addr)                                                        \
    asm volatile("ldmatrix.sync.aligned.m8n8.x4.shared.b16 {%0,%1,%2,%3}, [%4];" \
                 : "=r"((r)[0]), "=r"((r)[1]), "=r"((r)[2]), "=r"((r)[3])      \
                 : "r"(addr))

#define MMA_BF16(d, a, b)                                                     \
    asm volatile("mma.sync.aligned.m16n8k16.row.col.f32.bf16.bf16.f32 "        \
                 "{%0,%1,%2,%3}, {%4,%5,%6,%7}, {%8,%9}, {%0,%1,%2,%3};"       \
                 : "+f"((d)[0]), "+f"((d)[1]), "+f"((d)[2]), "+f"((d)[3])      \
                 : "r"((a)[0]), "r"((a)[1]), "r"((a)[2]), "r"((a)[3]),         \
                   "r"((b)[0]), "r"((b)[1]))

// ---------------------------------------------------------------------------
// Weight transpose + split: W[K,N] fp32 -> Th/Tl[N,K] bf16
// ---------------------------------------------------------------------------
__global__ void wsplit_kernel(const float* __restrict__ W,
                              __nv_bfloat16* __restrict__ Th,
                              __nv_bfloat16* __restrict__ Tl,
                              int K, int N)
{
    __shared__ float t[32][33];
    const int k0 = blockIdx.y * 32, n0 = blockIdx.x * 32;
    const int tx = threadIdx.x, ty = threadIdx.y;   // 32 x 8
#pragma unroll
    for (int i = 0; i < 32; i += 8)
        t[ty + i][tx] = W[(size_t)(k0 + ty + i) * N + n0 + tx];
    __syncthreads();
#pragma unroll
    for (int i = 0; i < 32; i += 8) {
        const float v = t[tx][ty + i];
        __nv_bfloat16 hi, lo;
        bf16_split(v, hi, lo);
        const size_t o = (size_t)(n0 + ty + i) * K + k0 + tx;
        Th[o] = hi; Tl[o] = lo;
    }
}

// ---------------------------------------------------------------------------
// Transpose small mamba weights for coalesced access
// ---------------------------------------------------------------------------
__global__ void mamba_prep_kernel(const float* __restrict__ conv_w,
                                  const float* __restrict__ xp_w,
                                  float* __restrict__ cwT,
                                  float* __restrict__ xpT)
{
    const int c = threadIdx.x;   // 512 threads, 1 block
#pragma unroll
    for (int w = 0; w < 3; ++w)  cwT[w * 512 + c] = conv_w[c * 3 + w];
#pragma unroll
    for (int j = 0; j < 16; ++j) xpT[j * 512 + c] = xp_w[c * 16 + j];
}

// ---------------------------------------------------------------------------
// Input projection: h = x @ w0 + b0 (K=8), also write bf16 split
// ---------------------------------------------------------------------------
__global__ void input_proj_kernel(const float* __restrict__ x,
                                  const float* __restrict__ w0,
                                  const float* __restrict__ b0,
                                  float* __restrict__ h,
                                  __nv_bfloat16* __restrict__ hh,
                                  __nv_bfloat16* __restrict__ hl)
{
    const int tok = blockIdx.x;
    const int n   = threadIdx.x;
    const float* xr = x + (size_t)tok * 8;
    float s = b0[n];
#pragma unroll
    for (int k = 0; k < 8; ++k) s += xr[k] * w0[k * 512 + n];
    const size_t o = (size_t)tok * 512 + n;
    h[o] = s;
    __nv_bfloat16 hi, lo;
    bf16_split(s, hi, lo);
    hh[o] = hi; hl[o] = lo;
}

// ---------------------------------------------------------------------------
// bf16x3 tensor-core GEMM via mma.sync:
//   C[M,N] = A @ Wt^T + bias (+ res),  A: [M,K] hi/lo, Wt: [N,K] hi/lo
// 256 threads (8 warps, 2m x 4n, warp tile 64x32), double-buffered cp.async,
// one barrier per k-tile. Compensation terms issued TERM-OUTER so consecutive
// MMAs hit distinct accumulators (no RAW chain on acc). 2 CTAs/SM.
// ---------------------------------------------------------------------------
__global__ __launch_bounds__(256, 2)
void gemm_bf16x3_kernel(const __nv_bfloat16* __restrict__ Ah,
                        const __nv_bfloat16* __restrict__ Al,
                        const __nv_bfloat16* __restrict__ Bh,
                        const __nv_bfloat16* __restrict__ Bl,
                        const float* __restrict__ bias,
                        const float* __restrict__ res,
                        float* __restrict__ C,
                        int N, int K)
{
    extern __shared__ char dsm[];
    __shared__ float s_bias[BN];

    const int tid  = threadIdx.x;
    const int lane = tid & 31;
    const int warp = tid >> 5;
    const int bm   = blockIdx.y * BM;
    const int bn   = blockIdx.x * BN;
    const uint32_t sbase = smem_u32(dsm);

    if (tid < BN) s_bias[tid] = bias[bn + tid];

    const size_t ld = (size_t)K * 2;          // bytes per source row
    const char* src0 = (const char*)Ah + (size_t)bm * ld;
    const char* src1 = (const char*)Al + (size_t)bm * ld;
    const char* src2 = (const char*)Bh + (size_t)bn * ld;
    const char* src3 = (const char*)Bl + (size_t)bn * ld;

    const int KT = K / BK;

#define LOAD_STAGE(kt_)                                                        \
    do {                                                                       \
        const uint32_t sb_ = sbase + (uint32_t)((kt_) % NST) * STG_BYTES;      \
        const size_t ko_ = (size_t)(kt_) * (BK * 2);                           \
        const char* s4_[4] = {src0 + ko_, src1 + ko_, src2 + ko_, src3 + ko_}; \
        _Pragma("unroll")                                                      \
        for (int t4 = 0; t4 < 4; ++t4) {                                       \
            const uint32_t tb_ = sb_ + t4 * TILE_BYTES;                        \
            _Pragma("unroll")                                                  \
            for (int it = 0; it < 2; ++it) {                                   \
                const int idx = it * 256 + tid;                                \
                const int r = idx >> 2, c = (idx & 3) * 16;                    \
                const uint32_t d_ = tb_ + (uint32_t)(r * 80 + c);              \
                const char* s_ = s4_[t4] + (size_t)r * ld + c;                 \
                asm volatile("cp.async.cg.shared.global [%0], [%1], 16;"       \
                             :: "r"(d_), "l"(s_) : "memory");                  \
            }                                                                  \
        }                                                                      \
        asm volatile("cp.async.commit_group;" ::: "memory");                   \
    } while (0)

    float acc[4][4][4];
#pragma unroll
    for (int i = 0; i < 4; ++i)
#pragma unroll
        for (int j = 0; j < 4; ++j)
#pragma unroll
            for (int q = 0; q < 4; ++q) acc[i][j][q] = 0.f;

    LOAD_STAGE(0);
    asm volatile("cp.async.wait_group 0;" ::: "memory");
    __syncthreads();

    const int wm = (warp >> 2) * 64;
    const int wn = (warp & 3) * 32;
    // ldmatrix lane mappings (non-trans)
    const int a_r = lane & 15;                 // row within 16-row atom
    const int a_k = (lane >> 4) * 8;           // k-half select
    const int b_n = (lane >> 4) * 8 + (lane & 7);
    const int b_k = ((lane >> 3) & 1) * 8;

    for (int kt = 0; kt < KT; ++kt) {
        // prefetch next stage into the other buffer (overlaps compute below)
        if (kt + 1 < KT) LOAD_STAGE(kt + 1);

        const uint32_t sb = sbase + (uint32_t)(kt % NST) * STG_BYTES;
#pragma unroll
        for (int ks = 0; ks < 2; ++ks) {
            const int k0 = ks * 16;
            uint32_t fbh[4][2], fbl[4][2];
#pragma unroll
            for (int p = 0; p < 2; ++p) {
                const uint32_t bd = sb + 2u * TILE_BYTES +
                    (uint32_t)(((wn + p * 16 + b_n) * SMEM_ROW_ELEM + k0 + b_k) * 2);
                uint32_t r4[4];
                LDSM4(r4, bd);
                fbh[2*p][0] = r4[0]; fbh[2*p][1] = r4[1];
                fbh[2*p+1][0] = r4[2]; fbh[2*p+1][1] = r4[3];
                LDSM4(r4, bd + TILE_BYTES);
                fbl[2*p][0] = r4[0]; fbl[2*p][1] = r4[1];
                fbl[2*p+1][0] = r4[2]; fbl[2*p+1][1] = r4[3];
            }
            // stream A fragments per m-atom; issue the 3 compensation terms
            // TERM-OUTER so consecutive MMAs target different accumulators
#pragma unroll
            for (int am = 0; am < 4; ++am) {
                const uint32_t ad = sb +
                    (uint32_t)(((wm + am * 16 + a_r) * SMEM_ROW_ELEM + k0 + a_k) * 2);
                uint32_t ah[4], al[4];
                LDSM4(ah, ad);
                LDSM4(al, ad + TILE_BYTES);
#pragma unroll
                for (int an = 0; an < 4; ++an) MMA_BF16(acc[am][an], ah, fbh[an]);
#pragma unroll
                for (int an = 0; an < 4; ++an) MMA_BF16(acc[am][an], al, fbh[an]);
#pragma unroll
                for (int an = 0; an < 4; ++an) MMA_BF16(acc[am][an], ah, fbl[an]);
            }
        }

        // next stage arrived + everyone done reading stage kt
        if (kt + 1 < KT) {
            asm volatile("cp.async.wait_group 0;" ::: "memory");
            __syncthreads();
        }
    }
#undef LOAD_STAGE

    // epilogue: acc (am,an): q0:(r,c) q1:(r,c+1) q2:(r+8,c) q3:(r+8,c+1)
    const int er = lane >> 2;
    const int ec = (lane & 3) * 2;
#pragma unroll
    for (int am = 0; am < 4; ++am) {
#pragma unroll
        for (int an = 0; an < 4; ++an) {
            const int row = bm + wm + am * 16 + er;
            const int lcol = wn + an * 8 + ec;
            const int col = bn + lcol;
            const float b0 = s_bias[lcol], b1 = s_bias[lcol + 1];
            float2 v0, v1;
            v0.x = acc[am][an][0] + b0;  v0.y = acc[am][an][1] + b1;
            v1.x = acc[am][an][2] + b0;  v1.y = acc[am][an][3] + b1;
            float* p0 = C + (size_t)row * N + col;
            float* p1 = C + (size_t)(row + 8) * N + col;
            if (res != nullptr) {
                const float2 r0 = *(const float2*)(res + (size_t)row * N + col);
                const float2 r1 = *(const float2*)(res + (size_t)(row + 8) * N + col);
                v0.x += r0.x; v0.y += r0.y;
                v1.x += r1.x; v1.y += r1.y;
            }
            *(float2*)p0 = v0;
            *(float2*)p1 = v1;
        }
    }
}

// ---------------------------------------------------------------------------
// Mamba middle: depthwise conv(3) + silu + dt path + gating + silu(z)
// Vectorized: 128 threads x 4 contiguous channels, float4 loads, packed
// bf16x2 stores. Uses TRANSPOSED weights (cwT[3][512], xpT[16][512]).
// ---------------------------------------------------------------------------
__global__ void mamba_mid_kernel(const float* __restrict__ zi,
                                 const float* __restrict__ cwT,
                                 const float* __restrict__ conv_b,
                                 const float* __restrict__ xpT,
                                 const float* __restrict__ xp_b,
                                 const float* __restrict__ dt_w,
                                 const float* __restrict__ dt_b,
                                 __nv_bfloat16* __restrict__ uh,
                                 __nv_bfloat16* __restrict__ ul)
{
    const int tok = blockIdx.x;
    const int l   = tok & (LSEQ - 1);
    const int t   = threadIdx.x;        // 128
    const int c0  = t * 4;              // 4 contiguous channels
    const float* xi0 = zi + (size_t)tok * 1024 + 512;

    const float4 zero4 = make_float4(0.f, 0.f, 0.f, 0.f);
    const float4 xm = (l > 0)        ? *(const float4*)(xi0 + c0 - 1024) : zero4;
    const float4 x0 = *(const float4*)(xi0 + c0);
    const float4 xq = (l < LSEQ - 1) ? *(const float4*)(xi0 + c0 + 1024) : zero4;
    const float4 w0v = *(const float4*)(cwT + c0);
    const float4 w1v = *(const float4*)(cwT + 512 + c0);
    const float4 w2v = *(const float4*)(cwT + 1024 + c0);
    const float4 cb  = *(const float4*)(conv_b + c0);

    float v[4];
    v[0] = xm.x * w0v.x + x0.x * w1v.x + xq.x * w2v.x + cb.x;
    v[1] = xm.y * w0v.y + x0.y * w1v.y + xq.y * w2v.y + cb.y;
    v[2] = xm.z * w0v.z + x0.z * w1v.z + xq.z * w2v.z + cb.z;
    v[3] = xm.w * w0v.w + x0.w * w1v.w + xq.w * w2v.w + cb.w;
#pragma unroll
    for (int i = 0; i < 4; ++i) v[i] = v[i] / (1.f + expf(-v[i]));   // silu

    float p[16];
#pragma unroll
    for (int j = 0; j < 16; ++j) {
        const float4 xw = *(const float4*)(xpT + j * 512 + c0);
        p[j] = v[0] * xw.x + v[1] * xw.y + v[2] * xw.z + v[3] * xw.w;
    }

    __shared__ float sred[4][16];
    const int lane = t & 31, warp = t >> 5;
#pragma unroll
    for (int j = 0; j < 16; ++j) {
        float pv = p[j];
#pragma unroll
        for (int off = 16; off; off >>= 1)
            pv += __shfl_xor_sync(0xffffffffu, pv, off);
        if (lane == 0) sred[warp][j] = pv;
    }
    __syncthreads();
#pragma unroll
    for (int j = 0; j < 16; ++j)
        p[j] = sred[0][j] + sred[1][j] + sred[2][j] + sred[3][j] + xp_b[j];

    // dt path: 4 channels per thread
    const float4 db = *(const float4*)(dt_b + c0);
    float q[4] = {db.x, db.y, db.z, db.w};
#pragma unroll
    for (int j = 0; j < 16; ++j) {
        const float4 dw = *(const float4*)(dt_w + j * 512 + c0);
        q[0] += p[j] * dw.x; q[1] += p[j] * dw.y;
        q[2] += p[j] * dw.z; q[3] += p[j] * dw.w;
    }

    float xv[4];
#pragma unroll
    for (int i = 0; i < 4; ++i) {
        const float dt = (q[i] > 20.f) ? q[i] : log1pf(expf(q[i]));  // softplus
        xv[i] = v[i] * dt;
    }

    // silu(z) for the same 4 channels
    const float* zrow = zi + (size_t)tok * 1024;
    const float4 z4 = *(const float4*)(zrow + c0);
    float sz[4];
    sz[0] = z4.x / (1.f + expf(-z4.x));
    sz[1] = z4.y / (1.f + expf(-z4.y));
    sz[2] = z4.z / (1.f + expf(-z4.z));
    sz[3] = z4.w / (1.f + expf(-z4.w));

    __nv_bfloat16* uhr = uh + (size_t)tok * 1024;
    __nv_bfloat16* ulr = ul + (size_t)tok * 1024;
    // hi/lo split + packed 8B stores
    float hi[4], lo[4];
#pragma unroll
    for (int i = 0; i < 4; ++i) {
        const float h = __bfloat162float(__float2bfloat16(xv[i]));
        hi[i] = h; lo[i] = xv[i] - h;
    }
    {
        uint2 sh_, sl_;
        sh_.x = pack_bf16x2(hi[0], hi[1]); sh_.y = pack_bf16x2(hi[2], hi[3]);
        sl_.x = pack_bf16x2(lo[0], lo[1]); sl_.y = pack_bf16x2(lo[2], lo[3]);
        *(uint2*)(uhr + c0) = sh_;
        *(uint2*)(ulr + c0) = sl_;
    }
#pragma unroll
    for (int i = 0; i < 4; ++i) {
        const float h = __bfloat162float(__float2bfloat16(sz[i]));
        hi[i] = h; lo[i] = sz[i] - h;
    }
    {
        uint2 sh_, sl_;
        sh_.x = pack_bf16x2(hi[0], hi[1]); sh_.y = pack_bf16x2(hi[2], hi[3]);
        sl_.x = pack_bf16x2(lo[0], lo[1]); sl_.y = pack_bf16x2(lo[2], lo[3]);
        *(uint2*)(uhr + 512 + c0) = sh_;
        *(uint2*)(ulr + 512 + c0) = sl_;
    }
}

// ---------------------------------------------------------------------------
// LayerNorm over H=512 per token (vectorized), writes h fp32 (+ bf16 split)
// ---------------------------------------------------------------------------
__global__ void layernorm_kernel(const float* __restrict__ tin,
                                 const float* __restrict__ gam,
                                 const float* __restrict__ bet,
                                 float* __restrict__ hout,
                                 __nv_bfloat16* __restrict__ hh,
                                 __nv_bfloat16* __restrict__ hl,
                                 int write_split)
{
    const int tok = blockIdx.x;
    const int t   = threadIdx.x;        // 128
    const int c0  = t * 4;
    const int lane = t & 31, warp = t >> 5;
    __shared__ float sh[4];

    const float4 v4 = *(const float4*)(tin + (size_t)tok * 512 + c0);
    float v[4] = {v4.x, v4.y, v4.z, v4.w};

    float s = v[0] + v[1] + v[2] + v[3];
#pragma unroll
    for (int off = 16; off; off >>= 1) s += __shfl_xor_sync(0xffffffffu, s, off);
    if (lane == 0) sh[warp] = s;
    __syncthreads();
    const float mu = (sh[0] + sh[1] + sh[2] + sh[3]) * (1.f / 512.f);
    __syncthreads();

    float q = 0.f;
#pragma unroll
    for (int i = 0; i < 4; ++i) { const float d = v[i] - mu; q += d * d; }
#pragma unroll
    for (int off = 16; off; off >>= 1) q += __shfl_xor_sync(0xffffffffu, q, off);
    if (lane == 0) sh[warp] = q;
    __syncthreads();
    const float var = (sh[0] + sh[1] + sh[2] + sh[3]) * (1.f / 512.f);
    const float rs  = rsqrtf(var + 1e-5f);

    const float4 g4 = *(const float4*)(gam + c0);
    const float4 b4 = *(const float4*)(bet + c0);
    float o[4];
    o[0] = (v[0] - mu) * rs * g4.x + b4.x;
    o[1] = (v[1] - mu) * rs * g4.y + b4.y;
    o[2] = (v[2] - mu) * rs * g4.z + b4.z;
    o[3] = (v[3] - mu) * rs * g4.w + b4.w;

    *(float4*)(hout + (size_t)tok * 512 + c0) = make_float4(o[0], o[1], o[2], o[3]);

    if (write_split) {
        float hi[4], lo[4];
#pragma unroll
        for (int i = 0; i < 4; ++i) {
            const float h = __bfloat162float(__float2bfloat16(o[i]));
            hi[i] = h; lo[i] = o[i] - h;
        }
        uint2 sh_, sl_;
        sh_.x = pack_bf16x2(hi[0], hi[1]); sh_.y = pack_bf16x2(hi[2], hi[3]);
        sl_.x = pack_bf16x2(lo[0], lo[1]); sl_.y = pack_bf16x2(lo[2], lo[3]);
        *(uint2*)(hh + (size_t)tok * 512 + c0) = sh_;
        *(uint2*)(hl + (size_t)tok * 512 + c0) = sl_;
    }
}

// ---------------------------------------------------------------------------
// reg = mean over L, dec = last token.
// ---------------------------------------------------------------------------
__global__ void reduce_kernel(const float* __restrict__ h,
                              float* __restrict__ reg,
                              float* __restrict__ dec)
{
    const int b = blockIdx.x;
    const int f = threadIdx.x;
    const float* base = h + (size_t)b * LSEQ * 512 + f;
    float s = 0.f;
#pragma unroll 8
    for (int l = 0; l < LSEQ; ++l) s += base[(size_t)l * 512];
    reg[b * 512 + f] = s * (1.f / (float)LSEQ);
    dec[b * 512 + f] = base[(size_t)(LSEQ - 1) * 512];
}

// ---------------------------------------------------------------------------
// Heads: gate argmax (softmax monotone; straight-through gate == one-hot),
// expert actor/critic projections.
// out layout: [logits 512*3][value 512][gate 512*4]
// ---------------------------------------------------------------------------
__global__ void heads_kernel(const float* __restrict__ reg,
                             const float* __restrict__ dec,
                             const float* __restrict__ gumbel,
                             const float* __restrict__ gate_w,
                             const float* __restrict__ gate_b,
                             const float* __restrict__ actor_w,
                             const float* __restrict__ actor_b,
                             const float* __restrict__ critic_w,
                             const float* __restrict__ critic_b,
                             float* __restrict__ out)
{
    const int b = blockIdx.x;
    const int t = threadIdx.x;
    const int lane = t & 31, warp = t >> 5;
    __shared__ float sred[4][4];

    float gl[4] = {0.f, 0.f, 0.f, 0.f};
    for (int hh = t; hh < 512; hh += 128) {
        const float r = reg[b * 512 + hh];
#pragma unroll
        for (int e = 0; e < 4; ++e) gl[e] += r * gate_w[hh * 4 + e];
    }
#pragma unroll
    for (int e = 0; e < 4; ++e) {
        float pv = gl[e];
#pragma unroll
        for (int off = 16; off; off >>= 1)
            pv += __shfl_xor_sync(0xffffffffu, pv, off);
        gl[e] = pv;
    }
    if (lane == 0) {
#pragma unroll
        for (int e = 0; e < 4; ++e) sred[warp][e] = gl[e];
    }
    __syncthreads();
#pragma unroll
    for (int e = 0; e < 4; ++e)
        gl[e] = sred[0][e] + sred[1][e] + sred[2][e] + sred[3][e]
              + gate_b[e] + gumbel[b * 4 + e];

    int es = 0;
#pragma unroll
    for (int e = 1; e < 4; ++e) if (gl[e] > gl[es]) es = e;
    __syncthreads();

    float acc[4] = {0.f, 0.f, 0.f, 0.f};
    const float* aw = actor_w + (size_t)es * 512 * 3;
    const float* cw = critic_w + (size_t)es * 512;
    for (int hh = t; hh < 512; hh += 128) {
        const float d = dec[b * 512 + hh];
        acc[0] += d * aw[hh * 3 + 0];
        acc[1] += d * aw[hh * 3 + 1];
        acc[2] += d * aw[hh * 3 + 2];
        acc[3] += d * cw[hh];
    }
#pragma unroll
    for (int e = 0; e < 4; ++e) {
        float pv = acc[e];
#pragma unroll
        for (int off = 16; off; off >>= 1)
            pv += __shfl_xor_sync(0xffffffffu, pv, off);
        acc[e] = pv;
    }
    if (lane == 0) {
#pragma unroll
        for (int e = 0; e < 4; ++e) sred[warp][e] = acc[e];
    }
    __syncthreads();

    if (t == 0) {
#pragma unroll
        for (int a = 0; a < 3; ++a)
            out[b * 3 + a] = sred[0][a] + sred[1][a] + sred[2][a] + sred[3][a]
                           + actor_b[es * 3 + a];
        out[512 * 3 + b] = sred[0][3] + sred[1][3] + sred[2][3] + sred[3][3]
                         + critic_b[es];
    }
    if (t < 4)
        out[512 * 3 + 512 + b * 4 + t] = (t == es) ? 1.0f : 0.0f;
}

// ---------------------------------------------------------------------------
// Launch. Input ordering probed via in_sizes (see R3 notes).
// ---------------------------------------------------------------------------
extern "C" void kernel_launch(void* const* d_in, const int* in_sizes, int n_in,
                              void* d_out, int out_size)
{
    const bool dict_order = (in_sizes[4] != 512 * 1024);

    const float* x      = (const float*)d_in[0];
    const float* gumbel = (const float*)d_in[1];
    const float* w0     = (const float*)d_in[2];
    const float* b0     = (const float*)d_in[3];

    int i_lng, i_m1, i_m2;
    if (dict_order) { i_lng = 4;  i_m1 = 12; i_m2 = 22; }
    else            { i_lng = 24; i_m1 = 4;  i_m2 = 14; }

    const float* ln_g     = (const float*)d_in[i_lng + 0];
    const float* ln_b     = (const float*)d_in[i_lng + 1];
    const float* gate_w   = (const float*)d_in[i_lng + 2];
    const float* gate_b   = (const float*)d_in[i_lng + 3];
    const float* actor_w  = (const float*)d_in[i_lng + 4];
    const float* actor_b  = (const float*)d_in[i_lng + 5];
    const float* critic_w = (const float*)d_in[i_lng + 6];
    const float* critic_b = (const float*)d_in[i_lng + 7];

    float *h, *zi, *tb, *reg, *dec, *cwT, *xpT;
    __nv_bfloat16 *hh, *hl, *uh, *ul, *wth, *wtl;
    cudaGetSymbolAddress((void**)&h,   g_h);
    cudaGetSymbolAddress((void**)&hh,  g_hh);
    cudaGetSymbolAddress((void**)&hl,  g_hl);
    cudaGetSymbolAddress((void**)&zi,  g_zi);
    cudaGetSymbolAddress((void**)&uh,  g_uh);
    cudaGetSymbolAddress((void**)&ul,  g_ul);
    cudaGetSymbolAddress((void**)&tb,  g_t);
    cudaGetSymbolAddress((void**)&wth, g_wth);
    cudaGetSymbolAddress((void**)&wtl, g_wtl);
    cudaGetSymbolAddress((void**)&cwT, g_cwT);
    cudaGetSymbolAddress((void**)&xpT, g_xpT);
    cudaGetSymbolAddress((void**)&reg, g_reg);
    cudaGetSymbolAddress((void**)&dec, g_dec);

    cudaFuncSetAttribute(gemm_bf16x3_kernel,
                         cudaFuncAttributeMaxDynamicSharedMemorySize, SMEM_DYN);

    input_proj_kernel<<<NTOK, 512>>>(x, w0, b0, h, hh, hl);

    for (int m = 0; m < 2; ++m) {
        const int base = (m == 0) ? i_m1 : i_m2;
        const float* in_w   = (const float*)d_in[base + 0];
        const float* in_b   = (const float*)d_in[base + 1];
        const float* conv_w = (const float*)d_in[base + 2];
        const float* conv_b = (const float*)d_in[base + 3];
        const float* xp_w   = (const float*)d_in[base + 4];
        const float* xp_b   = (const float*)d_in[base + 5];
        const float* dt_w   = (const float*)d_in[base + 6];
        const float* dt_b   = (const float*)d_in[base + 7];
        const float* out_w  = (const float*)d_in[base + 8];
        const float* out_b  = (const float*)d_in[base + 9];

        // Wt = split(in_w^T): [1024, 512]; transpose small weights
        wsplit_kernel<<<dim3(1024 / 32, 512 / 32), dim3(32, 8)>>>(
            in_w, wth, wtl, 512, 1024);
        mamba_prep_kernel<<<1, 512>>>(conv_w, xp_w, cwT, xpT);

        // zi = h @ in_w + in_b   (M=65536, N=1024, K=512)
        gemm_bf16x3_kernel<<<dim3(1024 / BN, NTOK / BM), 256, SMEM_DYN>>>(
            hh, hl, wth, wtl, in_b, nullptr, zi, 1024, 512);

        // conv + silu + dt gating -> u (bf16 split)
        mamba_mid_kernel<<<NTOK, 128>>>(zi, cwT, conv_b, xpT, xp_b,
                                        dt_w, dt_b, uh, ul);

        // Wt = split(out_w^T): [512, 1024]
        wsplit_kernel<<<dim3(512 / 32, 1024 / 32), dim3(32, 8)>>>(
            out_w, wth, wtl, 1024, 512);

        // t = u @ out_w + out_b + h   (M=65536, N=512, K=1024)
        gemm_bf16x3_kernel<<<dim3(512 / BN, NTOK / BM), 256, SMEM_DYN>>>(
            uh, ul, wth, wtl, out_b, h, tb, 512, 1024);

        // h = layernorm(t); final layer skips dead bf16-split stores
        layernorm_kernel<<<NTOK, 128>>>(tb, ln_g, ln_b, h, hh, hl,
                                        (m == 0) ? 1 : 0);
    }

    reduce_kernel<<<BATCH, 512>>>(h, reg, dec);

    heads_kernel<<<BATCH, 128>>>(reg, dec, gumbel, gate_w, gate_b,
                                 actor_w, actor_b, critic_w, critic_b,
                                 (float*)d_out);
}

// round 17
// speedup vs baseline: 1.2594x; 1.2594x over previous
#include <cuda_runtime.h>
#include <cuda_fp16.h>
#include <math.h>
#include <stdint.h>
#include <stddef.h>

// Problem constants
#define BATCH 512
#define LSEQ  128
#define HDIM  512
#define NTOK  (BATCH * LSEQ)   // 65536

// GEMM tile config (mma.sync path — base ISA only)
// fp16 2-term compensated: D = Ah*Bh + Al*Bh  (dropped Ah*Bl ~ 2^-12)
#define BM 128
#define BN 128
#define BK 32
#define SMEM_ROW_ELEM 40                    // 32 data + 8 pad (80B rows)
#define TILE_BYTES (BM * SMEM_ROW_ELEM * 2) // 10240 B per operand tile
#define STG_BYTES  (3 * TILE_BYTES)         // Ah,Al,Bh = 30720 B
#define NST 2
#define SMEM_DYN (NST * STG_BYTES)          // 61440 B -> 2 CTAs/SM

// ---------------------------------------------------------------------------
// Scratch (device globals: allocation-free, graph-capture safe)
// ---------------------------------------------------------------------------
__device__ float  g_h  [(size_t)NTOK * HDIM];        // fp32 h (residual)
__device__ __half g_hh [(size_t)NTOK * HDIM];        // h hi (fp16)
__device__ __half g_hl [(size_t)NTOK * HDIM];        // h lo (fp16)
__device__ float  g_zi [(size_t)NTOK * 2 * HDIM];    // in-proj out [z|xi]
__device__ __half g_uh [(size_t)NTOK * 2 * HDIM];    // u hi
__device__ __half g_ul [(size_t)NTOK * 2 * HDIM];    // u lo
__device__ float  g_t  [(size_t)NTOK * HDIM];        // pre-layernorm
__device__ __half g_wt [(size_t)1024 * 512];         // Wt fp16 [N,K]
__device__ float  g_cwT[3 * 512];                    // conv_w transposed
__device__ float  g_xpT[16 * 512];                   // xp_w transposed
__device__ float g_reg[BATCH * HDIM];
__device__ float g_dec[BATCH * HDIM];

// ---------------------------------------------------------------------------
// helpers
// ---------------------------------------------------------------------------
__device__ __forceinline__ uint32_t smem_u32(const void* p) {
    return (uint32_t)__cvta_generic_to_shared(p);
}

__device__ __forceinline__ void fp16_split(float v, __half& hi, __half& lo) {
    hi = __float2half(v);
    lo = __float2half(v - __half2float(hi));
}

__device__ __forceinline__ uint32_t pack_half2(float a, float b) {
    __half2 p = __halves2half2(__float2half(a), __float2half(b));
    return *(uint32_t*)&p;
}

#define LDSM4(r, addr)                                                        \
    asm volatile("ldmatrix.sync.aligned.m8n8.x4.shared.b16 {%0,%1,%2,%3}, [%4];" \
                 : "=r"((r)[0]), "=r"((r)[1]), "=r"((r)[2]), "=r"((r)[3])      \
                 : "r"(addr))

#define MMA_F16(d, a, b)                                                      \
    asm volatile("mma.sync.aligned.m16n8k16.row.col.f32.f16.f16.f32 "          \
                 "{%0,%1,%2,%3}, {%4,%5,%6,%7}, {%8,%9}, {%0,%1,%2,%3};"       \
                 : "+f"((d)[0]), "+f"((d)[1]), "+f"((d)[2]), "+f"((d)[3])      \
                 : "r"((a)[0]), "r"((a)[1]), "r"((a)[2]), "r"((a)[3]),         \
                   "r"((b)[0]), "r"((b)[1]))

// ---------------------------------------------------------------------------
// Weight transpose: W[K,N] fp32 -> T[N,K] fp16
// ---------------------------------------------------------------------------
__global__ void wsplit_kernel(const float* __restrict__ W,
                              __half* __restrict__ T,
                              int K, int N)
{
    __shared__ float t[32][33];
    const int k0 = blockIdx.y * 32, n0 = blockIdx.x * 32;
    const int tx = threadIdx.x, ty = threadIdx.y;   // 32 x 8
#pragma unroll
    for (int i = 0; i < 32; i += 8)
        t[ty + i][tx] = W[(size_t)(k0 + ty + i) * N + n0 + tx];
    __syncthreads();
#pragma unroll
    for (int i = 0; i < 32; i += 8)
        T[(size_t)(n0 + ty + i) * K + k0 + tx] = __float2half(t[tx][ty + i]);
}

// ---------------------------------------------------------------------------
// Transpose small mamba weights for coalesced access
// ---------------------------------------------------------------------------
__global__ void mamba_prep_kernel(const float* __restrict__ conv_w,
                                  const float* __restrict__ xp_w,
                                  float* __restrict__ cwT,
                                  float* __restrict__ xpT)
{
    const int c = threadIdx.x;   // 512 threads, 1 block
#pragma unroll
    for (int w = 0; w < 3; ++w)  cwT[w * 512 + c] = conv_w[c * 3 + w];
#pragma unroll
    for (int j = 0; j < 16; ++j) xpT[j * 512 + c] = xp_w[c * 16 + j];
}

// ---------------------------------------------------------------------------
// Input projection: h = x @ w0 + b0 (K=8), also write fp16 split
// ---------------------------------------------------------------------------
__global__ void input_proj_kernel(const float* __restrict__ x,
                                  const float* __restrict__ w0,
                                  const float* __restrict__ b0,
                                  float* __restrict__ h,
                                  __half* __restrict__ hh,
                                  __half* __restrict__ hl)
{
    const int tok = blockIdx.x;
    const int n   = threadIdx.x;
    const float* xr = x + (size_t)tok * 8;
    float s = b0[n];
#pragma unroll
    for (int k = 0; k < 8; ++k) s += xr[k] * w0[k * 512 + n];
    const size_t o = (size_t)tok * 512 + n;
    h[o] = s;
    __half hi, lo;
    fp16_split(s, hi, lo);
    hh[o] = hi; hl[o] = lo;
}

// ---------------------------------------------------------------------------
// fp16x2 tensor-core GEMM via mma.sync:
//   C[M,N] = A @ Wt^T + bias (+ res),  A: [M,K] hi/lo fp16, Wt: [N,K] fp16
// 256 threads (8 warps, 2m x 4n, warp tile 64x32), double-buffered cp.async,
// one barrier per k-tile, 2 CTAs/SM.
// ---------------------------------------------------------------------------
__global__ __launch_bounds__(256, 2)
void gemm_fp16x2_kernel(const __half* __restrict__ Ah,
                        const __half* __restrict__ Al,
                        const __half* __restrict__ Bh,
                        const float* __restrict__ bias,
                        const float* __restrict__ res,
                        float* __restrict__ C,
                        int N, int K)
{
    extern __shared__ char dsm[];
    __shared__ float s_bias[BN];

    const int tid  = threadIdx.x;
    const int lane = tid & 31;
    const int warp = tid >> 5;
    const int bm   = blockIdx.y * BM;
    const int bn   = blockIdx.x * BN;
    const uint32_t sbase = smem_u32(dsm);

    if (tid < BN) s_bias[tid] = bias[bn + tid];

    const size_t ld = (size_t)K * 2;          // bytes per source row
    const char* src0 = (const char*)Ah + (size_t)bm * ld;
    const char* src1 = (const char*)Al + (size_t)bm * ld;
    const char* src2 = (const char*)Bh + (size_t)bn * ld;

    const int KT = K / BK;

#define LOAD_STAGE(kt_)                                                        \
    do {                                                                       \
        const uint32_t sb_ = sbase + (uint32_t)((kt_) % NST) * STG_BYTES;      \
        const size_t ko_ = (size_t)(kt_) * (BK * 2);                           \
        const char* s3_[3] = {src0 + ko_, src1 + ko_, src2 + ko_};             \
        _Pragma("unroll")                                                      \
        for (int t3 = 0; t3 < 3; ++t3) {                                       \
            const uint32_t tb_ = sb_ + t3 * TILE_BYTES;                        \
            _Pragma("unroll")                                                  \
            for (int it = 0; it < 2; ++it) {                                   \
                const int idx = it * 256 + tid;                                \
                const int r = idx >> 2, c = (idx & 3) * 16;                    \
                const uint32_t d_ = tb_ + (uint32_t)(r * 80 + c);              \
                const char* s_ = s3_[t3] + (size_t)r * ld + c;                 \
                asm volatile("cp.async.cg.shared.global [%0], [%1], 16;"       \
                             :: "r"(d_), "l"(s_) : "memory");                  \
            }                                                                  \
        }                                                                      \
        asm volatile("cp.async.commit_group;" ::: "memory");                   \
    } while (0)

    float acc[4][4][4];
#pragma unroll
    for (int i = 0; i < 4; ++i)
#pragma unroll
        for (int j = 0; j < 4; ++j)
#pragma unroll
            for (int q = 0; q < 4; ++q) acc[i][j][q] = 0.f;

    LOAD_STAGE(0);
    asm volatile("cp.async.wait_group 0;" ::: "memory");
    __syncthreads();

    const int wm = (warp >> 2) * 64;
    const int wn = (warp & 3) * 32;
    // ldmatrix lane mappings (non-trans)
    const int a_r = lane & 15;                 // row within 16-row atom
    const int a_k = (lane >> 4) * 8;           // k-half select
    const int b_n = (lane >> 4) * 8 + (lane & 7);
    const int b_k = ((lane >> 3) & 1) * 8;

    for (int kt = 0; kt < KT; ++kt) {
        // prefetch next stage into the other buffer (overlaps compute below)
        if (kt + 1 < KT) LOAD_STAGE(kt + 1);

        const uint32_t sb = sbase + (uint32_t)(kt % NST) * STG_BYTES;
#pragma unroll
        for (int ks = 0; ks < 2; ++ks) {
            const int k0 = ks * 16;
            uint32_t fbh[4][2];
#pragma unroll
            for (int p = 0; p < 2; ++p) {
                const uint32_t bd = sb + 2u * TILE_BYTES +
                    (uint32_t)(((wn + p * 16 + b_n) * SMEM_ROW_ELEM + k0 + b_k) * 2);
                uint32_t r4[4];
                LDSM4(r4, bd);
                fbh[2*p][0] = r4[0]; fbh[2*p][1] = r4[1];
                fbh[2*p+1][0] = r4[2]; fbh[2*p+1][1] = r4[3];
            }
            // stream A fragments per m-atom (hi + lo), 2 compensation terms
#pragma unroll
            for (int am = 0; am < 4; ++am) {
                const uint32_t ad = sb +
                    (uint32_t)(((wm + am * 16 + a_r) * SMEM_ROW_ELEM + k0 + a_k) * 2);
                uint32_t ah[4], al[4];
                LDSM4(ah, ad);
                LDSM4(al, ad + TILE_BYTES);
#pragma unroll
                for (int an = 0; an < 4; ++an) MMA_F16(acc[am][an], ah, fbh[an]);
#pragma unroll
                for (int an = 0; an < 4; ++an) MMA_F16(acc[am][an], al, fbh[an]);
            }
        }

        // next stage arrived + everyone done reading stage kt
        if (kt + 1 < KT) {
            asm volatile("cp.async.wait_group 0;" ::: "memory");
            __syncthreads();
        }
    }
#undef LOAD_STAGE

    // epilogue: acc (am,an): q0:(r,c) q1:(r,c+1) q2:(r+8,c) q3:(r+8,c+1)
    const int er = lane >> 2;
    const int ec = (lane & 3) * 2;
#pragma unroll
    for (int am = 0; am < 4; ++am) {
#pragma unroll
        for (int an = 0; an < 4; ++an) {
            const int row = bm + wm + am * 16 + er;
            const int lcol = wn + an * 8 + ec;
            const int col = bn + lcol;
            const float b0 = s_bias[lcol], b1 = s_bias[lcol + 1];
            float2 v0, v1;
            v0.x = acc[am][an][0] + b0;  v0.y = acc[am][an][1] + b1;
            v1.x = acc[am][an][2] + b0;  v1.y = acc[am][an][3] + b1;
            float* p0 = C + (size_t)row * N + col;
            float* p1 = C + (size_t)(row + 8) * N + col;
            if (res != nullptr) {
                const float2 r0 = *(const float2*)(res + (size_t)row * N + col);
                const float2 r1 = *(const float2*)(res + (size_t)(row + 8) * N + col);
                v0.x += r0.x; v0.y += r0.y;
                v1.x += r1.x; v1.y += r1.y;
            }
            *(float2*)p0 = v0;
            *(float2*)p1 = v1;
        }
    }
}

// ---------------------------------------------------------------------------
// Mamba middle: depthwise conv(3) + silu + dt path + gating + silu(z)
// Vectorized: 128 threads x 4 contiguous channels, float4 loads, packed
// half2 stores. Uses TRANSPOSED weights (cwT[3][512], xpT[16][512]).
// ---------------------------------------------------------------------------
__global__ void mamba_mid_kernel(const float* __restrict__ zi,
                                 const float* __restrict__ cwT,
                                 const float* __restrict__ conv_b,
                                 const float* __restrict__ xpT,
                                 const float* __restrict__ xp_b,
                                 const float* __restrict__ dt_w,
                                 const float* __restrict__ dt_b,
                                 __half* __restrict__ uh,
                                 __half* __restrict__ ul)
{
    const int tok = blockIdx.x;
    const int l   = tok & (LSEQ - 1);
    const int t   = threadIdx.x;        // 128
    const int c0  = t * 4;              // 4 contiguous channels
    const float* xi0 = zi + (size_t)tok * 1024 + 512;

    const float4 zero4 = make_float4(0.f, 0.f, 0.f, 0.f);
    const float4 xm = (l > 0)        ? *(const float4*)(xi0 + c0 - 1024) : zero4;
    const float4 x0 = *(const float4*)(xi0 + c0);
    const float4 xq = (l < LSEQ - 1) ? *(const float4*)(xi0 + c0 + 1024) : zero4;
    const float4 w0v = *(const float4*)(cwT + c0);
    const float4 w1v = *(const float4*)(cwT + 512 + c0);
    const float4 w2v = *(const float4*)(cwT + 1024 + c0);
    const float4 cb  = *(const float4*)(conv_b + c0);

    float v[4];
    v[0] = xm.x * w0v.x + x0.x * w1v.x + xq.x * w2v.x + cb.x;
    v[1] = xm.y * w0v.y + x0.y * w1v.y + xq.y * w2v.y + cb.y;
    v[2] = xm.z * w0v.z + x0.z * w1v.z + xq.z * w2v.z + cb.z;
    v[3] = xm.w * w0v.w + x0.w * w1v.w + xq.w * w2v.w + cb.w;
#pragma unroll
    for (int i = 0; i < 4; ++i) v[i] = v[i] / (1.f + expf(-v[i]));   // silu

    float p[16];
#pragma unroll
    for (int j = 0; j < 16; ++j) {
        const float4 xw = *(const float4*)(xpT + j * 512 + c0);
        p[j] = v[0] * xw.x + v[1] * xw.y + v[2] * xw.z + v[3] * xw.w;
    }

    __shared__ float sred[4][16];
    const int lane = t & 31, warp = t >> 5;
#pragma unroll
    for (int j = 0; j < 16; ++j) {
        float pv = p[j];
#pragma unroll
        for (int off = 16; off; off >>= 1)
            pv += __shfl_xor_sync(0xffffffffu, pv, off);
        if (lane == 0) sred[warp][j] = pv;
    }
    __syncthreads();
#pragma unroll
    for (int j = 0; j < 16; ++j)
        p[j] = sred[0][j] + sred[1][j] + sred[2][j] + sred[3][j] + xp_b[j];

    // dt path: 4 channels per thread
    const float4 db = *(const float4*)(dt_b + c0);
    float q[4] = {db.x, db.y, db.z, db.w};
#pragma unroll
    for (int j = 0; j < 16; ++j) {
        const float4 dw = *(const float4*)(dt_w + j * 512 + c0);
        q[0] += p[j] * dw.x; q[1] += p[j] * dw.y;
        q[2] += p[j] * dw.z; q[3] += p[j] * dw.w;
    }

    float xv[4];
#pragma unroll
    for (int i = 0; i < 4; ++i) {
        const float dt = (q[i] > 20.f) ? q[i] : log1pf(expf(q[i]));  // softplus
        xv[i] = v[i] * dt;
    }

    // silu(z) for the same 4 channels
    const float* zrow = zi + (size_t)tok * 1024;
    const float4 z4 = *(const float4*)(zrow + c0);
    float sz[4];
    sz[0] = z4.x / (1.f + expf(-z4.x));
    sz[1] = z4.y / (1.f + expf(-z4.y));
    sz[2] = z4.z / (1.f + expf(-z4.z));
    sz[3] = z4.w / (1.f + expf(-z4.w));

    __half* uhr = uh + (size_t)tok * 1024;
    __half* ulr = ul + (size_t)tok * 1024;
    // hi/lo split + packed 8B stores
    float hi[4], lo[4];
#pragma unroll
    for (int i = 0; i < 4; ++i) {
        const float h = __half2float(__float2half(xv[i]));
        hi[i] = h; lo[i] = xv[i] - h;
    }
    {
        uint2 sh_, sl_;
        sh_.x = pack_half2(hi[0], hi[1]); sh_.y = pack_half2(hi[2], hi[3]);
        sl_.x = pack_half2(lo[0], lo[1]); sl_.y = pack_half2(lo[2], lo[3]);
        *(uint2*)(uhr + c0) = sh_;
        *(uint2*)(ulr + c0) = sl_;
    }
#pragma unroll
    for (int i = 0; i < 4; ++i) {
        const float h = __half2float(__float2half(sz[i]));
        hi[i] = h; lo[i] = sz[i] - h;
    }
    {
        uint2 sh_, sl_;
        sh_.x = pack_half2(hi[0], hi[1]); sh_.y = pack_half2(hi[2], hi[3]);
        sl_.x = pack_half2(lo[0], lo[1]); sl_.y = pack_half2(lo[2], lo[3]);
        *(uint2*)(uhr + 512 + c0) = sh_;
        *(uint2*)(ulr + 512 + c0) = sl_;
    }
}

// ---------------------------------------------------------------------------
// LayerNorm over H=512 per token (vectorized), writes h fp32 (+ fp16 split)
// ---------------------------------------------------------------------------
__global__ void layernorm_kernel(const float* __restrict__ tin,
                                 const float* __restrict__ gam,
                                 const float* __restrict__ bet,
                                 float* __restrict__ hout,
                                 __half* __restrict__ hh,
                                 __half* __restrict__ hl,
                                 int write_split)
{
    const int tok = blockIdx.x;
    const int t   = threadIdx.x;        // 128
    const int c0  = t * 4;
    const int lane = t & 31, warp = t >> 5;
    __shared__ float sh[4];

    const float4 v4 = *(const float4*)(tin + (size_t)tok * 512 + c0);
    float v[4] = {v4.x, v4.y, v4.z, v4.w};

    float s = v[0] + v[1] + v[2] + v[3];
#pragma unroll
    for (int off = 16; off; off >>= 1) s += __shfl_xor_sync(0xffffffffu, s, off);
    if (lane == 0) sh[warp] = s;
    __syncthreads();
    const float mu = (sh[0] + sh[1] + sh[2] + sh[3]) * (1.f / 512.f);
    __syncthreads();

    float q = 0.f;
#pragma unroll
    for (int i = 0; i < 4; ++i) { const float d = v[i] - mu; q += d * d; }
#pragma unroll
    for (int off = 16; off; off >>= 1) q += __shfl_xor_sync(0xffffffffu, q, off);
    if (lane == 0) sh[warp] = q;
    __syncthreads();
    const float var = (sh[0] + sh[1] + sh[2] + sh[3]) * (1.f / 512.f);
    const float rs  = rsqrtf(var + 1e-5f);

    const float4 g4 = *(const float4*)(gam + c0);
    const float4 b4 = *(const float4*)(bet + c0);
    float o[4];
    o[0] = (v[0] - mu) * rs * g4.x + b4.x;
    o[1] = (v[1] - mu) * rs * g4.y + b4.y;
    o[2] = (v[2] - mu) * rs * g4.z + b4.z;
    o[3] = (v[3] - mu) * rs * g4.w + b4.w;

    *(float4*)(hout + (size_t)tok * 512 + c0) = make_float4(o[0], o[1], o[2], o[3]);

    if (write_split) {
        float hi[4], lo[4];
#pragma unroll
        for (int i = 0; i < 4; ++i) {
            const float h = __half2float(__float2half(o[i]));
            hi[i] = h; lo[i] = o[i] - h;
        }
        uint2 sh_, sl_;
        sh_.x = pack_half2(hi[0], hi[1]); sh_.y = pack_half2(hi[2], hi[3]);
        sl_.x = pack_half2(lo[0], lo[1]); sl_.y = pack_half2(lo[2], lo[3]);
        *(uint2*)(hh + (size_t)tok * 512 + c0) = sh_;
        *(uint2*)(hl + (size_t)tok * 512 + c0) = sl_;
    }
}

// ---------------------------------------------------------------------------
// reg = mean over L, dec = last token.
// ---------------------------------------------------------------------------
__global__ void reduce_kernel(const float* __restrict__ h,
                              float* __restrict__ reg,
                              float* __restrict__ dec)
{
    const int b = blockIdx.x;
    const int f = threadIdx.x;
    const float* base = h + (size_t)b * LSEQ * 512 + f;
    float s = 0.f;
#pragma unroll 8
    for (int l = 0; l < LSEQ; ++l) s += base[(size_t)l * 512];
    reg[b * 512 + f] = s * (1.f / (float)LSEQ);
    dec[b * 512 + f] = base[(size_t)(LSEQ - 1) * 512];
}

// ---------------------------------------------------------------------------
// Heads: gate argmax (softmax monotone; straight-through gate == one-hot),
// expert actor/critic projections.
// out layout: [logits 512*3][value 512][gate 512*4]
// ---------------------------------------------------------------------------
__global__ void heads_kernel(const float* __restrict__ reg,
                             const float* __restrict__ dec,
                             const float* __restrict__ gumbel,
                             const float* __restrict__ gate_w,
                             const float* __restrict__ gate_b,
                             const float* __restrict__ actor_w,
                             const float* __restrict__ actor_b,
                             const float* __restrict__ critic_w,
                             const float* __restrict__ critic_b,
                             float* __restrict__ out)
{
    const int b = blockIdx.x;
    const int t = threadIdx.x;
    const int lane = t & 31, warp = t >> 5;
    __shared__ float sred[4][4];

    float gl[4] = {0.f, 0.f, 0.f, 0.f};
    for (int hh = t; hh < 512; hh += 128) {
        const float r = reg[b * 512 + hh];
#pragma unroll
        for (int e = 0; e < 4; ++e) gl[e] += r * gate_w[hh * 4 + e];
    }
#pragma unroll
    for (int e = 0; e < 4; ++e) {
        float pv = gl[e];
#pragma unroll
        for (int off = 16; off; off >>= 1)
            pv += __shfl_xor_sync(0xffffffffu, pv, off);
        gl[e] = pv;
    }
    if (lane == 0) {
#pragma unroll
        for (int e = 0; e < 4; ++e) sred[warp][e] = gl[e];
    }
    __syncthreads();
#pragma unroll
    for (int e = 0; e < 4; ++e)
        gl[e] = sred[0][e] + sred[1][e] + sred[2][e] + sred[3][e]
              + gate_b[e] + gumbel[b * 4 + e];

    int es = 0;
#pragma unroll
    for (int e = 1; e < 4; ++e) if (gl[e] > gl[es]) es = e;
    __syncthreads();

    float acc[4] = {0.f, 0.f, 0.f, 0.f};
    const float* aw = actor_w + (size_t)es * 512 * 3;
    const float* cw = critic_w + (size_t)es * 512;
    for (int hh = t; hh < 512; hh += 128) {
        const float d = dec[b * 512 + hh];
        acc[0] += d * aw[hh * 3 + 0];
        acc[1] += d * aw[hh * 3 + 1];
        acc[2] += d * aw[hh * 3 + 2];
        acc[3] += d * cw[hh];
    }
#pragma unroll
    for (int e = 0; e < 4; ++e) {
        float pv = acc[e];
#pragma unroll
        for (int off = 16; off; off >>= 1)
            pv += __shfl_xor_sync(0xffffffffu, pv, off);
        acc[e] = pv;
    }
    if (lane == 0) {
#pragma unroll
        for (int e = 0; e < 4; ++e) sred[warp][e] = acc[e];
    }
    __syncthreads();

    if (t == 0) {
#pragma unroll
        for (int a = 0; a < 3; ++a)
            out[b * 3 + a] = sred[0][a] + sred[1][a] + sred[2][a] + sred[3][a]
                           + actor_b[es * 3 + a];
        out[512 * 3 + b] = sred[0][3] + sred[1][3] + sred[2][3] + sred[3][3]
                         + critic_b[es];
    }
    if (t < 4)
        out[512 * 3 + 512 + b * 4 + t] = (t == es) ? 1.0f : 0.0f;
}

// ---------------------------------------------------------------------------
// Launch. Input ordering probed via in_sizes (see R3 notes).
// ---------------------------------------------------------------------------
extern "C" void kernel_launch(void* const* d_in, const int* in_sizes, int n_in,
                              void* d_out, int out_size)
{
    const bool dict_order = (in_sizes[4] != 512 * 1024);

    const float* x      = (const float*)d_in[0];
    const float* gumbel = (const float*)d_in[1];
    const float* w0     = (const float*)d_in[2];
    const float* b0     = (const float*)d_in[3];

    int i_lng, i_m1, i_m2;
    if (dict_order) { i_lng = 4;  i_m1 = 12; i_m2 = 22; }
    else            { i_lng = 24; i_m1 = 4;  i_m2 = 14; }

    const float* ln_g     = (const float*)d_in[i_lng + 0];
    const float* ln_b     = (const float*)d_in[i_lng + 1];
    const float* gate_w   = (const float*)d_in[i_lng + 2];
    const float* gate_b   = (const float*)d_in[i_lng + 3];
    const float* actor_w  = (const float*)d_in[i_lng + 4];
    const float* actor_b  = (const float*)d_in[i_lng + 5];
    const float* critic_w = (const float*)d_in[i_lng + 6];
    const float* critic_b = (const float*)d_in[i_lng + 7];

    float *h, *zi, *tb, *reg, *dec, *cwT, *xpT;
    __half *hh, *hl, *uh, *ul, *wt;
    cudaGetSymbolAddress((void**)&h,   g_h);
    cudaGetSymbolAddress((void**)&hh,  g_hh);
    cudaGetSymbolAddress((void**)&hl,  g_hl);
    cudaGetSymbolAddress((void**)&zi,  g_zi);
    cudaGetSymbolAddress((void**)&uh,  g_uh);
    cudaGetSymbolAddress((void**)&ul,  g_ul);
    cudaGetSymbolAddress((void**)&tb,  g_t);
    cudaGetSymbolAddress((void**)&wt,  g_wt);
    cudaGetSymbolAddress((void**)&cwT, g_cwT);
    cudaGetSymbolAddress((void**)&xpT, g_xpT);
    cudaGetSymbolAddress((void**)&reg, g_reg);
    cudaGetSymbolAddress((void**)&dec, g_dec);

    cudaFuncSetAttribute(gemm_fp16x2_kernel,
                         cudaFuncAttributeMaxDynamicSharedMemorySize, SMEM_DYN);

    input_proj_kernel<<<NTOK, 512>>>(x, w0, b0, h, hh, hl);

    for (int m = 0; m < 2; ++m) {
        const int base = (m == 0) ? i_m1 : i_m2;
        const float* in_w   = (const float*)d_in[base + 0];
        const float* in_b   = (const float*)d_in[base + 1];
        const float* conv_w = (const float*)d_in[base + 2];
        const float* conv_b = (const float*)d_in[base + 3];
        const float* xp_w   = (const float*)d_in[base + 4];
        const float* xp_b   = (const float*)d_in[base + 5];
        const float* dt_w   = (const float*)d_in[base + 6];
        const float* dt_b   = (const float*)d_in[base + 7];
        const float* out_w  = (const float*)d_in[base + 8];
        const float* out_b  = (const float*)d_in[base + 9];

        // Wt = fp16(in_w^T): [1024, 512]; transpose small weights
        wsplit_kernel<<<dim3(1024 / 32, 512 / 32), dim3(32, 8)>>>(
            in_w, wt, 512, 1024);
        mamba_prep_kernel<<<1, 512>>>(conv_w, xp_w, cwT, xpT);

        // zi = h @ in_w + in_b   (M=65536, N=1024, K=512)
        gemm_fp16x2_kernel<<<dim3(1024 / BN, NTOK / BM), 256, SMEM_DYN>>>(
            hh, hl, wt, in_b, nullptr, zi, 1024, 512);

        // conv + silu + dt gating -> u (fp16 split)
        mamba_mid_kernel<<<NTOK, 128>>>(zi, cwT, conv_b, xpT, xp_b,
                                        dt_w, dt_b, uh, ul);

        // Wt = fp16(out_w^T): [512, 1024]
        wsplit_kernel<<<dim3(512 / 32, 1024 / 32), dim3(32, 8)>>>(
            out_w, wt, 1024, 512);

        // t = u @ out_w + out_b + h   (M=65536, N=512, K=1024)
        gemm_fp16x2_kernel<<<dim3(512 / BN, NTOK / BM), 256, SMEM_DYN>>>(
            uh, ul, wt, out_b, h, tb, 512, 1024);

        // h = layernorm(t); final layer skips dead fp16-split stores
        layernorm_kernel<<<NTOK, 128>>>(tb, ln_g, ln_b, h, hh, hl,
                                        (m == 0) ? 1 : 0);
    }

    reduce_kernel<<<BATCH, 512>>>(h, reg, dec);

    heads_kernel<<<BATCH, 128>>>(reg, dec, gumbel, gate_w, gate_b,
                                 actor_w, actor_b, critic_w, critic_b,
                                 (float*)d_out);
}